// round 10
// baseline (speedup 1.0000x reference)
#include <cuda_runtime.h>
#include <cstdint>

#define TT 2048
#define EE 256
#define HH 512
#define GBD 32         // blocks per direction in recurrent kernel
#define CPB 16         // cells per block
#define KK 48
#define NEGV -100000.0f
#define STARTT 45
#define ENDT 46

// ---------------- scratch (device globals; no allocation allowed) ----------------
__device__ float g_x[TT * EE];              // embedded tokens        2 MB
__device__ float g_proj0[TT * 4 * HH];      // input proj (fwd)      16 MB
__device__ float g_proj1[TT * 4 * HH];      // input proj (bwd)      16 MB
__device__ float g_h0[TT * 2 * HH];         // layer0 output          8 MB
__device__ float g_h1[TT * 2 * HH];         // layer1 output          8 MB
__device__ float g_feats[TT * KK];          // linear output
// packed {tag<<32 | h} per cell, double-buffered, per (layer,dir)
__device__ unsigned long long g_hx[4][2][HH];

#define FMA_F32X2(acc, a, b) \
    asm("fma.rn.f32x2 %0, %1, %2, %3;" : "=l"(acc) : "l"(a), "l"(b), "l"(acc))
#define UNPACK_F32X2(lo, hi, in) \
    asm("mov.b64 {%0, %1}, %2;" : "=f"(lo), "=f"(hi) : "l"(in))

__device__ __forceinline__ float tanh_approx(float x) {
    float r;
    asm("tanh.approx.f32 %0, %1;" : "=f"(r) : "f"(x));
    return r;
}

// ---------------- init: reset packed h slots every replay ----------------
__global__ void init_kernel() {
    int tid = threadIdx.x;
    unsigned long long* p = (unsigned long long*)g_hx;
    for (int i = tid; i < 4 * 2 * HH; i += 512) p[i] = 0ull;
}

// ---------------- embedding gather ----------------
__global__ void embed_kernel(const int* __restrict__ tok, const float* __restrict__ emb) {
    int i = blockIdx.x * 256 + threadIdx.x;        // i < TT*EE
    int t = i >> 8;
    int e = i & 255;
    g_x[i] = __ldg(&emb[tok[t] * EE + e]);
}

// ---------------- tiled SGEMM (dual: z=0 fwd weights -> g_proj0, z=1 bwd -> g_proj1)
__global__ __launch_bounds__(256) void gemm_kernel(const float* __restrict__ Wf,
                                                   const float* __restrict__ b1f,
                                                   const float* __restrict__ b2f,
                                                   const float* __restrict__ Wb,
                                                   const float* __restrict__ b1b,
                                                   const float* __restrict__ b2b,
                                                   int a_sel, int Kd) {
    const float* A = a_sel ? g_h0 : g_x;
    int zb = blockIdx.z;
    const float* W = zb ? Wb : Wf;
    const float* b1 = zb ? b1b : b1f;
    const float* b2 = zb ? b2b : b2f;
    float* C = zb ? g_proj1 : g_proj0;
    const int N = 2048;

    __shared__ float As[16][128];
    __shared__ float Ws[16][128];

    int tid = threadIdx.x;
    int m0 = blockIdx.y * 128, n0 = blockIdx.x * 128;
    int tx = tid & 15, ty = tid >> 4;
    int lr = tid >> 1;
    int kq = (tid & 1) * 8;

    float acc[8][8];
#pragma unroll
    for (int i = 0; i < 8; i++)
#pragma unroll
        for (int j = 0; j < 8; j++) acc[i][j] = 0.f;

    for (int kt = 0; kt < Kd; kt += 16) {
        float4 a0 = *(const float4*)&A[(m0 + lr) * Kd + kt + kq];
        float4 a1 = *(const float4*)&A[(m0 + lr) * Kd + kt + kq + 4];
        float4 w0 = *(const float4*)&W[(n0 + lr) * Kd + kt + kq];
        float4 w1 = *(const float4*)&W[(n0 + lr) * Kd + kt + kq + 4];
        __syncthreads();
        As[kq + 0][lr] = a0.x; As[kq + 1][lr] = a0.y; As[kq + 2][lr] = a0.z; As[kq + 3][lr] = a0.w;
        As[kq + 4][lr] = a1.x; As[kq + 5][lr] = a1.y; As[kq + 6][lr] = a1.z; As[kq + 7][lr] = a1.w;
        Ws[kq + 0][lr] = w0.x; Ws[kq + 1][lr] = w0.y; Ws[kq + 2][lr] = w0.z; Ws[kq + 3][lr] = w0.w;
        Ws[kq + 4][lr] = w1.x; Ws[kq + 5][lr] = w1.y; Ws[kq + 6][lr] = w1.z; Ws[kq + 7][lr] = w1.w;
        __syncthreads();
#pragma unroll
        for (int k = 0; k < 16; k++) {
            float4 av0 = *(const float4*)&As[k][ty * 8];
            float4 av1 = *(const float4*)&As[k][ty * 8 + 4];
            float4 bv0 = *(const float4*)&Ws[k][tx * 8];
            float4 bv1 = *(const float4*)&Ws[k][tx * 8 + 4];
            float a_[8] = {av0.x, av0.y, av0.z, av0.w, av1.x, av1.y, av1.z, av1.w};
            float b_[8] = {bv0.x, bv0.y, bv0.z, bv0.w, bv1.x, bv1.y, bv1.z, bv1.w};
#pragma unroll
            for (int i = 0; i < 8; i++)
#pragma unroll
                for (int j = 0; j < 8; j++) acc[i][j] += a_[i] * b_[j];
        }
    }

#pragma unroll
    for (int i = 0; i < 8; i++) {
        int row = m0 + ty * 8 + i;
#pragma unroll
        for (int j0 = 0; j0 < 8; j0 += 4) {
            int col = n0 + tx * 8 + j0;
            float4 v;
            v.x = acc[i][j0 + 0] + __ldg(&b1[col + 0]) + __ldg(&b2[col + 0]);
            v.y = acc[i][j0 + 1] + __ldg(&b1[col + 1]) + __ldg(&b2[col + 1]);
            v.z = acc[i][j0 + 2] + __ldg(&b1[col + 2]) + __ldg(&b2[col + 2]);
            v.w = acc[i][j0 + 3] + __ldg(&b1[col + 3]) + __ldg(&b2[col + 3]);
            *(float4*)&C[row * N + col] = v;
        }
    }
}

// ---------------- persistent bidirectional LSTM layer ----------------
// grid = 64 blocks: [0,32) fwd, [32,64) bwd. 512 threads = 16 warps.
// Warp w owns cell b*16+w. Lane = gate*8+s: 8-lane group computes gate,
// lane s covers h columns [64s, 64s+64). 3 butterfly levels + 4 broadcasts.
// Sync: packed {tag,h} u64 slots; threads 0-255 poll 2 slots via v2.u64.
__global__ __launch_bounds__(512) void lstm_layer(const float* __restrict__ whhf,
                                                  const float* __restrict__ whhb,
                                                  int outsel, int cb) {
    __shared__ float hsm[2][HH];    // double-buffered staged h

    int dir = (blockIdx.x >= GBD) ? 1 : 0;
    int b = blockIdx.x - dir * GBD;
    const float* proj = dir ? g_proj1 : g_proj0;
    const float* whh = dir ? whhb : whhf;
    float* hout = outsel ? g_h1 : g_h0;
    int tid = threadIdx.x;
    int w = tid >> 5, lane = tid & 31;
    int cell = b * CPB + w;
    int gate = lane >> 3, s = lane & 7;
    bool glead = (s == 0);

    // Weights: gate row (gate*HH+cell), cols [64s, 64s+64) = 16 ulonglong2.
    ulonglong2 wp[16];
    {
        const ulonglong2* row = (const ulonglong2*)(whh + (gate * HH + cell) * HH);
#pragma unroll
        for (int j = 0; j < 16; j++) wp[j] = row[s * 16 + j];
    }

    unsigned long long* hx0 = g_hx[cb + dir][0];
    unsigned long long* hx1 = g_hx[cb + dir][1];

    float c = 0.f;
    float pv = 0.f;
    {
        int tt0 = dir ? (TT - 1) : 0;
        if (glead) pv = __ldg(&proj[tt0 * 2048 + gate * HH + cell]);
    }

    unsigned junk = tid;
    for (int t = 0; t < TT; t++) {
        int tt = dir ? (TT - 1 - t) : t;
        unsigned long long* rbuf = (t & 1) ? hx1 : hx0;
        unsigned long long* wbuf = (t & 1) ? hx0 : hx1;
        float* hs = hsm[t & 1];

        // stage: threads 0-255 poll TWO adjacent slots with one 16B load.
        if (tid < 256) {
            unsigned long long v0, v1;
            const unsigned long long* sp = &rbuf[2 * tid];
            asm volatile("ld.global.cg.v2.u64 {%0,%1}, [%2];"
                         : "=l"(v0), "=l"(v1) : "l"(sp) : "memory");
            while ((int)(v0 >> 32) < t || (int)(v1 >> 32) < t) {
#pragma unroll
                for (int i = 0; i < 16; i++)
                    asm volatile("add.u32 %0, %0, 1;" : "+r"(junk));
                asm volatile("ld.global.cg.v2.u64 {%0,%1}, [%2];"
                             : "=l"(v0), "=l"(v1) : "l"(sp) : "memory");
            }
            float2 hv;
            hv.x = __uint_as_float((unsigned)v0);
            hv.y = __uint_as_float((unsigned)v1);
            *(float2*)&hs[2 * tid] = hv;
        }

        float pvc = pv;
        if (t + 1 < TT && glead) {
            int ttn = dir ? (TT - 2 - t) : (t + 1);
            pv = __ldg(&proj[ttn * 2048 + gate * HH + cell]);
        }
        __syncthreads();

        // 64-element slice of the 512-dot: 16 ulonglong2, 4-way ILP accumulators
        unsigned long long acc0 = 0, acc1 = 0, acc2 = 0, acc3 = 0;
        const ulonglong2* hp = (const ulonglong2*)hs;
#pragma unroll
        for (int j = 0; j < 4; j++) {
            ulonglong2 h0 = hp[s * 16 + 4 * j + 0];
            ulonglong2 h1 = hp[s * 16 + 4 * j + 1];
            ulonglong2 h2 = hp[s * 16 + 4 * j + 2];
            ulonglong2 h3 = hp[s * 16 + 4 * j + 3];
            FMA_F32X2(acc0, wp[4 * j + 0].x, h0.x);
            FMA_F32X2(acc0, wp[4 * j + 0].y, h0.y);
            FMA_F32X2(acc1, wp[4 * j + 1].x, h1.x);
            FMA_F32X2(acc1, wp[4 * j + 1].y, h1.y);
            FMA_F32X2(acc2, wp[4 * j + 2].x, h2.x);
            FMA_F32X2(acc2, wp[4 * j + 2].y, h2.y);
            FMA_F32X2(acc3, wp[4 * j + 3].x, h3.x);
            FMA_F32X2(acc3, wp[4 * j + 3].y, h3.y);
        }
        float g;
        {
            float lo0, hi0, lo1, hi1, lo2, hi2, lo3, hi3;
            UNPACK_F32X2(lo0, hi0, acc0);
            UNPACK_F32X2(lo1, hi1, acc1);
            UNPACK_F32X2(lo2, hi2, acc2);
            UNPACK_F32X2(lo3, hi3, acc3);
            g = (lo0 + hi0) + (lo1 + hi1) + ((lo2 + hi2) + (lo3 + hi3));
        }
        // reduce within 8-lane gate group
        g += __shfl_xor_sync(0xffffffffu, g, 1);
        g += __shfl_xor_sync(0xffffffffu, g, 2);
        g += __shfl_xor_sync(0xffffffffu, g, 4);
        if (glead) g += pvc;

        // group leaders compute activation via tanh.approx
        // sigmoid(x) = 0.5*tanh(0.5x)+0.5 ; gate 2 (g) is plain tanh
        float arg = (gate == 2) ? g : 0.5f * g;
        float tv = tanh_approx(arg);
        float y = (gate == 2) ? tv : fmaf(0.5f, tv, 0.5f);
        float iv = __shfl_sync(0xffffffffu, y, 0);
        float fv = __shfl_sync(0xffffffffu, y, 8);
        float gv = __shfl_sync(0xffffffffu, y, 16);
        float ov = __shfl_sync(0xffffffffu, y, 24);
        c = fv * c + iv * gv;          // uniform across lanes
        float h = ov * tanh_approx(c);

        if (lane == 0) {
            unsigned long long pkt =
                ((unsigned long long)(unsigned)(t + 1) << 32) | (unsigned long long)__float_as_uint(h);
            asm volatile("st.global.cg.u64 [%0], %1;" :: "l"(&wbuf[cell]), "l"(pkt) : "memory");
            hout[tt * (2 * HH) + dir * HH + cell] = h;
        }
        // hsm parity reuse is gated by the next step's barrier
    }
}

// ---------------- linear:  feats[T,K] = h1 @ lin_w^T + lin_b ----------------
__global__ __launch_bounds__(128) void linear_kernel(const float* __restrict__ lw,
                                                     const float* __restrict__ lb) {
    __shared__ float hs[2 * HH];
    int t = blockIdx.x, tid = threadIdx.x;
    for (int i = tid; i < (2 * HH) / 4; i += 128)
        ((float4*)hs)[i] = ((const float4*)(g_h1 + t * 2 * HH))[i];
    __syncthreads();
    int warp = tid >> 5, lane = tid & 31;
    for (int jj = warp; jj < KK; jj += 4) {
        const float* wrow = lw + jj * (2 * HH);
        float acc = 0.f;
#pragma unroll 8
        for (int k = 0; k < 32; k++) {
            int d = lane + 32 * k;
            acc += hs[d] * __ldg(&wrow[d]);
        }
        acc += __shfl_xor_sync(0xffffffffu, acc, 16);
        acc += __shfl_xor_sync(0xffffffffu, acc, 8);
        acc += __shfl_xor_sync(0xffffffffu, acc, 4);
        acc += __shfl_xor_sync(0xffffffffu, acc, 2);
        acc += __shfl_xor_sync(0xffffffffu, acc, 1);
        if (lane == 0) g_feats[t * KK + jj] = acc + __ldg(&lb[jj]);
    }
}

// ---------------- CRF forward scan + gold score + final output ----------------
__global__ __launch_bounds__(768) void crf_kernel(const float* __restrict__ trans,
                                                  const int* __restrict__ tags,
                                                  const int* __restrict__ seq_len,
                                                  float* __restrict__ out) {
    __shared__ float tr[KK * KK];
    __shared__ float alpha[2][KK];
    __shared__ float red[768];
    __shared__ float s_score;
    int tid = threadIdx.x;

    for (int i = tid; i < KK * KK; i += 768) tr[i] = trans[i];

    float sc = 0.f;
    for (int k = tid; k < TT; k += 768) {
        int cur = tags[k];
        int prev = (k == 0) ? STARTT : tags[k - 1];
        sc += __ldg(&trans[cur * KK + prev]) + __ldg(&g_feats[k * KK + cur]);
    }
    red[tid] = sc;
    if (tid < KK) alpha[0][tid] = (tid == STARTT) ? 0.f : NEGV;
    __syncthreads();
    if (tid == 0) {
        float s = 0.f;
        for (int i = 0; i < 768; i++) s += red[i];
        s += tr[ENDT * KK + tags[TT - 1]];
        s_score = s;
    }
    __syncthreads();

    int j = tid >> 4, l = tid & 15;
    for (int t = 0; t < TT; t++) {
        const float* a = alpha[t & 1];
        float* an = alpha[(t + 1) & 1];
        float v0 = a[l]      + tr[j * KK + l];
        float v1 = a[l + 16] + tr[j * KK + l + 16];
        float v2 = a[l + 32] + tr[j * KK + l + 32];
        float m = fmaxf(v0, fmaxf(v1, v2));
#pragma unroll
        for (int o = 8; o >= 1; o >>= 1) m = fmaxf(m, __shfl_xor_sync(0xffffffffu, m, o));
        float s = __expf(v0 - m) + __expf(v1 - m) + __expf(v2 - m);
#pragma unroll
        for (int o = 8; o >= 1; o >>= 1) s += __shfl_xor_sync(0xffffffffu, s, o);
        if (l == 0) an[j] = m + __logf(s) + __ldg(&g_feats[t * KK + j]);
        __syncthreads();
    }

    if (tid == 0) {
        const float* a = alpha[TT & 1];
        float m = -3.4e38f;
        for (int i = 0; i < KK; i++) m = fmaxf(m, a[i] + tr[ENDT * KK + i]);
        float s = 0.f;
        for (int i = 0; i < KK; i++) s += __expf(a[i] + tr[ENDT * KK + i] - m);
        float logz = m + __logf(s);
        out[0] = (logz - s_score) / (float)seq_len[0];
    }
}

// ---------------- launch ----------------
extern "C" void kernel_launch(void* const* d_in, const int* in_sizes, int n_in,
                              void* d_out, int out_size) {
    const int* tokens = (const int*)d_in[0];
    const int* tags = (const int*)d_in[1];
    const int* seq_len = (const int*)d_in[2];
    const float* embed = (const float*)d_in[3];
    const float* w_ih_l0_f = (const float*)d_in[4];
    const float* w_hh_l0_f = (const float*)d_in[5];
    const float* b_ih_l0_f = (const float*)d_in[6];
    const float* b_hh_l0_f = (const float*)d_in[7];
    const float* w_ih_l0_b = (const float*)d_in[8];
    const float* w_hh_l0_b = (const float*)d_in[9];
    const float* b_ih_l0_b = (const float*)d_in[10];
    const float* b_hh_l0_b = (const float*)d_in[11];
    const float* w_ih_l1_f = (const float*)d_in[12];
    const float* w_hh_l1_f = (const float*)d_in[13];
    const float* b_ih_l1_f = (const float*)d_in[14];
    const float* b_hh_l1_f = (const float*)d_in[15];
    const float* w_ih_l1_b = (const float*)d_in[16];
    const float* w_hh_l1_b = (const float*)d_in[17];
    const float* b_ih_l1_b = (const float*)d_in[18];
    const float* b_hh_l1_b = (const float*)d_in[19];
    const float* lin_w = (const float*)d_in[20];
    const float* lin_b = (const float*)d_in[21];
    const float* trans = (const float*)d_in[22];
    float* out = (float*)d_out;

    init_kernel<<<1, 512>>>();
    embed_kernel<<<(TT * EE) / 256, 256>>>(tokens, embed);

    gemm_kernel<<<dim3(16, 16, 2), 256>>>(w_ih_l0_f, b_ih_l0_f, b_hh_l0_f,
                                          w_ih_l0_b, b_ih_l0_b, b_hh_l0_b, 0, EE);
    lstm_layer<<<2 * GBD, 512>>>(w_hh_l0_f, w_hh_l0_b, 0, 0);

    gemm_kernel<<<dim3(16, 16, 2), 256>>>(w_ih_l1_f, b_ih_l1_f, b_hh_l1_f,
                                          w_ih_l1_b, b_ih_l1_b, b_hh_l1_b, 1, 2 * HH);
    lstm_layer<<<2 * GBD, 512>>>(w_hh_l1_f, w_hh_l1_b, 1, 2);

    linear_kernel<<<TT, 128>>>(lin_w, lin_b);
    crf_kernel<<<1, 768>>>(trans, tags, seq_len, out);
}

// round 11
// speedup vs baseline: 4.0454x; 4.0454x over previous
#include <cuda_runtime.h>
#include <cstdint>

#define TT 2048
#define EE 256
#define HH 512
#define GBD 32         // blocks per direction in recurrent kernel
#define CPB 16         // cells per block
#define KK 48
#define NEGV -100000.0f
#define STARTT 45
#define ENDT 46

// ---------------- scratch (device globals; no allocation allowed) ----------------
__device__ float g_x[TT * EE];              // embedded tokens        2 MB
__device__ float g_proj0[TT * 4 * HH];      // input proj (fwd)      16 MB
__device__ float g_proj1[TT * 4 * HH];      // input proj (bwd)      16 MB
__device__ float g_h0[TT * 2 * HH];         // layer0 output          8 MB
__device__ float g_h1[TT * 2 * HH];         // layer1 output          8 MB
__device__ float g_feats[TT * KK];          // linear output
// packed {tag<<32 | h} per cell, double-buffered, per (layer,dir)
__device__ unsigned long long g_hx[4][2][HH];

#define FMA_F32X2(acc, a, b) \
    asm("fma.rn.f32x2 %0, %1, %2, %3;" : "=l"(acc) : "l"(a), "l"(b), "l"(acc))
#define UNPACK_F32X2(lo, hi, in) \
    asm("mov.b64 {%0, %1}, %2;" : "=f"(lo), "=f"(hi) : "l"(in))

__device__ __forceinline__ float tanh_approx(float x) {
    float r;
    asm("tanh.approx.f32 %0, %1;" : "=f"(r) : "f"(x));
    return r;
}

// ---------------- init: reset packed h slots every replay ----------------
__global__ void init_kernel() {
    int tid = threadIdx.x;
    unsigned long long* p = (unsigned long long*)g_hx;
    for (int i = tid; i < 4 * 2 * HH; i += 512) p[i] = 0ull;
}

// ---------------- embedding gather ----------------
__global__ void embed_kernel(const int* __restrict__ tok, const float* __restrict__ emb) {
    int i = blockIdx.x * 256 + threadIdx.x;        // i < TT*EE
    int t = i >> 8;
    int e = i & 255;
    g_x[i] = __ldg(&emb[tok[t] * EE + e]);
}

// ---------------- tiled SGEMM (dual: z=0 fwd weights -> g_proj0, z=1 bwd -> g_proj1)
__global__ __launch_bounds__(256) void gemm_kernel(const float* __restrict__ Wf,
                                                   const float* __restrict__ b1f,
                                                   const float* __restrict__ b2f,
                                                   const float* __restrict__ Wb,
                                                   const float* __restrict__ b1b,
                                                   const float* __restrict__ b2b,
                                                   int a_sel, int Kd) {
    const float* A = a_sel ? g_h0 : g_x;
    int zb = blockIdx.z;
    const float* W = zb ? Wb : Wf;
    const float* b1 = zb ? b1b : b1f;
    const float* b2 = zb ? b2b : b2f;
    float* C = zb ? g_proj1 : g_proj0;
    const int N = 2048;

    __shared__ float As[16][128];
    __shared__ float Ws[16][128];

    int tid = threadIdx.x;
    int m0 = blockIdx.y * 128, n0 = blockIdx.x * 128;
    int tx = tid & 15, ty = tid >> 4;
    int lr = tid >> 1;
    int kq = (tid & 1) * 8;

    float acc[8][8];
#pragma unroll
    for (int i = 0; i < 8; i++)
#pragma unroll
        for (int j = 0; j < 8; j++) acc[i][j] = 0.f;

    for (int kt = 0; kt < Kd; kt += 16) {
        float4 a0 = *(const float4*)&A[(m0 + lr) * Kd + kt + kq];
        float4 a1 = *(const float4*)&A[(m0 + lr) * Kd + kt + kq + 4];
        float4 w0 = *(const float4*)&W[(n0 + lr) * Kd + kt + kq];
        float4 w1 = *(const float4*)&W[(n0 + lr) * Kd + kt + kq + 4];
        __syncthreads();
        As[kq + 0][lr] = a0.x; As[kq + 1][lr] = a0.y; As[kq + 2][lr] = a0.z; As[kq + 3][lr] = a0.w;
        As[kq + 4][lr] = a1.x; As[kq + 5][lr] = a1.y; As[kq + 6][lr] = a1.z; As[kq + 7][lr] = a1.w;
        Ws[kq + 0][lr] = w0.x; Ws[kq + 1][lr] = w0.y; Ws[kq + 2][lr] = w0.z; Ws[kq + 3][lr] = w0.w;
        Ws[kq + 4][lr] = w1.x; Ws[kq + 5][lr] = w1.y; Ws[kq + 6][lr] = w1.z; Ws[kq + 7][lr] = w1.w;
        __syncthreads();
#pragma unroll
        for (int k = 0; k < 16; k++) {
            float4 av0 = *(const float4*)&As[k][ty * 8];
            float4 av1 = *(const float4*)&As[k][ty * 8 + 4];
            float4 bv0 = *(const float4*)&Ws[k][tx * 8];
            float4 bv1 = *(const float4*)&Ws[k][tx * 8 + 4];
            float a_[8] = {av0.x, av0.y, av0.z, av0.w, av1.x, av1.y, av1.z, av1.w};
            float b_[8] = {bv0.x, bv0.y, bv0.z, bv0.w, bv1.x, bv1.y, bv1.z, bv1.w};
#pragma unroll
            for (int i = 0; i < 8; i++)
#pragma unroll
                for (int j = 0; j < 8; j++) acc[i][j] += a_[i] * b_[j];
        }
    }

#pragma unroll
    for (int i = 0; i < 8; i++) {
        int row = m0 + ty * 8 + i;
#pragma unroll
        for (int j0 = 0; j0 < 8; j0 += 4) {
            int col = n0 + tx * 8 + j0;
            float4 v;
            v.x = acc[i][j0 + 0] + __ldg(&b1[col + 0]) + __ldg(&b2[col + 0]);
            v.y = acc[i][j0 + 1] + __ldg(&b1[col + 1]) + __ldg(&b2[col + 1]);
            v.z = acc[i][j0 + 2] + __ldg(&b1[col + 2]) + __ldg(&b2[col + 2]);
            v.w = acc[i][j0 + 3] + __ldg(&b1[col + 3]) + __ldg(&b2[col + 3]);
            *(float4*)&C[row * N + col] = v;
        }
    }
}

// ---------------- persistent bidirectional LSTM layer ----------------
// grid = 64 blocks: [0,32) fwd, [32,64) bwd. 512 threads = 16 warps.
// Warp w owns cell b*16+w. Lane = gate*8+s: 8-lane group computes gate.
// Lane s covers INTERLEAVED chunks {s+8k} (16B each) -> banks 4s..4s+3,
// conflict-free across the group; gate groups broadcast (dedup).
// Sync (R6-proven): every thread polls ONE u64 slot, 16-add backoff.
__global__ __launch_bounds__(512) void lstm_layer(const float* __restrict__ whhf,
                                                  const float* __restrict__ whhb,
                                                  int outsel, int cb) {
    __shared__ float hsm[2][HH];    // double-buffered staged h

    int dir = (blockIdx.x >= GBD) ? 1 : 0;
    int b = blockIdx.x - dir * GBD;
    const float* proj = dir ? g_proj1 : g_proj0;
    const float* whh = dir ? whhb : whhf;
    float* hout = outsel ? g_h1 : g_h0;
    int tid = threadIdx.x;
    int w = tid >> 5, lane = tid & 31;
    int cell = b * CPB + w;
    int gate = lane >> 3, s = lane & 7;
    bool glead = (s == 0);

    // Weights: gate row (gate*HH+cell); lane s holds chunks {s+8k}, k=0..15.
    ulonglong2 wp[16];
    {
        const ulonglong2* row = (const ulonglong2*)(whh + (gate * HH + cell) * HH);
#pragma unroll
        for (int k = 0; k < 16; k++) wp[k] = row[s + 8 * k];
    }

    unsigned long long* hx0 = g_hx[cb + dir][0];
    unsigned long long* hx1 = g_hx[cb + dir][1];

    float c = 0.f;
    float pv = 0.f;
    {
        int tt0 = dir ? (TT - 1) : 0;
        if (glead) pv = __ldg(&proj[tt0 * 2048 + gate * HH + cell]);
    }

    unsigned junk = tid;
    for (int t = 0; t < TT; t++) {
        int tt = dir ? (TT - 1 - t) : t;
        unsigned long long* rbuf = (t & 1) ? hx1 : hx0;
        unsigned long long* wbuf = (t & 1) ? hx0 : hx1;
        float* hs = hsm[t & 1];

        // stage: every thread polls its own slot; tag>=t means value present.
        {
            unsigned long long v;
            const unsigned long long* sp = &rbuf[tid];
            asm volatile("ld.global.cg.u64 %0, [%1];" : "=l"(v) : "l"(sp) : "memory");
            while ((int)(v >> 32) < t) {
#pragma unroll
                for (int i = 0; i < 16; i++)
                    asm volatile("add.u32 %0, %0, 1;" : "+r"(junk));
                asm volatile("ld.global.cg.u64 %0, [%1];" : "=l"(v) : "l"(sp) : "memory");
            }
            hs[tid] = __uint_as_float((unsigned)v);
        }

        float pvc = pv;
        if (t + 1 < TT && glead) {
            int ttn = dir ? (TT - 2 - t) : (t + 1);
            pv = __ldg(&proj[ttn * 2048 + gate * HH + cell]);
        }
        __syncthreads();

        // 64-element slice of the 512-dot: 16 interleaved ulonglong2, 4-way ILP
        unsigned long long acc0 = 0, acc1 = 0, acc2 = 0, acc3 = 0;
        const ulonglong2* hp = (const ulonglong2*)hs;
#pragma unroll
        for (int k = 0; k < 4; k++) {
            ulonglong2 h0 = hp[s + 8 * (4 * k + 0)];
            ulonglong2 h1 = hp[s + 8 * (4 * k + 1)];
            ulonglong2 h2 = hp[s + 8 * (4 * k + 2)];
            ulonglong2 h3 = hp[s + 8 * (4 * k + 3)];
            FMA_F32X2(acc0, wp[4 * k + 0].x, h0.x);
            FMA_F32X2(acc0, wp[4 * k + 0].y, h0.y);
            FMA_F32X2(acc1, wp[4 * k + 1].x, h1.x);
            FMA_F32X2(acc1, wp[4 * k + 1].y, h1.y);
            FMA_F32X2(acc2, wp[4 * k + 2].x, h2.x);
            FMA_F32X2(acc2, wp[4 * k + 2].y, h2.y);
            FMA_F32X2(acc3, wp[4 * k + 3].x, h3.x);
            FMA_F32X2(acc3, wp[4 * k + 3].y, h3.y);
        }
        float g;
        {
            float lo0, hi0, lo1, hi1, lo2, hi2, lo3, hi3;
            UNPACK_F32X2(lo0, hi0, acc0);
            UNPACK_F32X2(lo1, hi1, acc1);
            UNPACK_F32X2(lo2, hi2, acc2);
            UNPACK_F32X2(lo3, hi3, acc3);
            g = (lo0 + hi0) + (lo1 + hi1) + ((lo2 + hi2) + (lo3 + hi3));
        }
        // reduce within 8-lane gate group
        g += __shfl_xor_sync(0xffffffffu, g, 1);
        g += __shfl_xor_sync(0xffffffffu, g, 2);
        g += __shfl_xor_sync(0xffffffffu, g, 4);
        if (glead) g += pvc;

        // group leaders compute activation via tanh.approx
        // sigmoid(x) = 0.5*tanh(0.5x)+0.5 ; gate 2 (g) is plain tanh
        float arg = (gate == 2) ? g : 0.5f * g;
        float tv = tanh_approx(arg);
        float y = (gate == 2) ? tv : fmaf(0.5f, tv, 0.5f);
        float iv = __shfl_sync(0xffffffffu, y, 0);
        float fv = __shfl_sync(0xffffffffu, y, 8);
        float gv = __shfl_sync(0xffffffffu, y, 16);
        float ov = __shfl_sync(0xffffffffu, y, 24);
        c = fv * c + iv * gv;          // uniform across lanes
        float h = ov * tanh_approx(c);

        if (lane == 0) {
            unsigned long long pkt =
                ((unsigned long long)(unsigned)(t + 1) << 32) | (unsigned long long)__float_as_uint(h);
            asm volatile("st.global.cg.u64 [%0], %1;" :: "l"(&wbuf[cell]), "l"(pkt) : "memory");
            hout[tt * (2 * HH) + dir * HH + cell] = h;
        }
        // hsm parity reuse is gated by the next step's barrier
    }
}

// ---------------- linear:  feats[T,K] = h1 @ lin_w^T + lin_b ----------------
__global__ __launch_bounds__(128) void linear_kernel(const float* __restrict__ lw,
                                                     const float* __restrict__ lb) {
    __shared__ float hs[2 * HH];
    int t = blockIdx.x, tid = threadIdx.x;
    for (int i = tid; i < (2 * HH) / 4; i += 128)
        ((float4*)hs)[i] = ((const float4*)(g_h1 + t * 2 * HH))[i];
    __syncthreads();
    int warp = tid >> 5, lane = tid & 31;
    for (int jj = warp; jj < KK; jj += 4) {
        const float* wrow = lw + jj * (2 * HH);
        float acc = 0.f;
#pragma unroll 8
        for (int k = 0; k < 32; k++) {
            int d = lane + 32 * k;
            acc += hs[d] * __ldg(&wrow[d]);
        }
        acc += __shfl_xor_sync(0xffffffffu, acc, 16);
        acc += __shfl_xor_sync(0xffffffffu, acc, 8);
        acc += __shfl_xor_sync(0xffffffffu, acc, 4);
        acc += __shfl_xor_sync(0xffffffffu, acc, 2);
        acc += __shfl_xor_sync(0xffffffffu, acc, 1);
        if (lane == 0) g_feats[t * KK + jj] = acc + __ldg(&lb[jj]);
    }
}

// ---------------- CRF forward scan + gold score + final output ----------------
__global__ __launch_bounds__(768) void crf_kernel(const float* __restrict__ trans,
                                                  const int* __restrict__ tags,
                                                  const int* __restrict__ seq_len,
                                                  float* __restrict__ out) {
    __shared__ float tr[KK * KK];
    __shared__ float alpha[2][KK];
    __shared__ float red[768];
    __shared__ float s_score;
    int tid = threadIdx.x;

    for (int i = tid; i < KK * KK; i += 768) tr[i] = trans[i];

    float sc = 0.f;
    for (int k = tid; k < TT; k += 768) {
        int cur = tags[k];
        int prev = (k == 0) ? STARTT : tags[k - 1];
        sc += __ldg(&trans[cur * KK + prev]) + __ldg(&g_feats[k * KK + cur]);
    }
    red[tid] = sc;
    if (tid < KK) alpha[0][tid] = (tid == STARTT) ? 0.f : NEGV;
    __syncthreads();
    if (tid == 0) {
        float s = 0.f;
        for (int i = 0; i < 768; i++) s += red[i];
        s += tr[ENDT * KK + tags[TT - 1]];
        s_score = s;
    }
    __syncthreads();

    int j = tid >> 4, l = tid & 15;
    for (int t = 0; t < TT; t++) {
        const float* a = alpha[t & 1];
        float* an = alpha[(t + 1) & 1];
        float v0 = a[l]      + tr[j * KK + l];
        float v1 = a[l + 16] + tr[j * KK + l + 16];
        float v2 = a[l + 32] + tr[j * KK + l + 32];
        float m = fmaxf(v0, fmaxf(v1, v2));
#pragma unroll
        for (int o = 8; o >= 1; o >>= 1) m = fmaxf(m, __shfl_xor_sync(0xffffffffu, m, o));
        float s = __expf(v0 - m) + __expf(v1 - m) + __expf(v2 - m);
#pragma unroll
        for (int o = 8; o >= 1; o >>= 1) s += __shfl_xor_sync(0xffffffffu, s, o);
        if (l == 0) an[j] = m + __logf(s) + __ldg(&g_feats[t * KK + j]);
        __syncthreads();
    }

    if (tid == 0) {
        const float* a = alpha[TT & 1];
        float m = -3.4e38f;
        for (int i = 0; i < KK; i++) m = fmaxf(m, a[i] + tr[ENDT * KK + i]);
        float s = 0.f;
        for (int i = 0; i < KK; i++) s += __expf(a[i] + tr[ENDT * KK + i] - m);
        float logz = m + __logf(s);
        out[0] = (logz - s_score) / (float)seq_len[0];
    }
}

// ---------------- launch ----------------
extern "C" void kernel_launch(void* const* d_in, const int* in_sizes, int n_in,
                              void* d_out, int out_size) {
    const int* tokens = (const int*)d_in[0];
    const int* tags = (const int*)d_in[1];
    const int* seq_len = (const int*)d_in[2];
    const float* embed = (const float*)d_in[3];
    const float* w_ih_l0_f = (const float*)d_in[4];
    const float* w_hh_l0_f = (const float*)d_in[5];
    const float* b_ih_l0_f = (const float*)d_in[6];
    const float* b_hh_l0_f = (const float*)d_in[7];
    const float* w_ih_l0_b = (const float*)d_in[8];
    const float* w_hh_l0_b = (const float*)d_in[9];
    const float* b_ih_l0_b = (const float*)d_in[10];
    const float* b_hh_l0_b = (const float*)d_in[11];
    const float* w_ih_l1_f = (const float*)d_in[12];
    const float* w_hh_l1_f = (const float*)d_in[13];
    const float* b_ih_l1_f = (const float*)d_in[14];
    const float* b_hh_l1_f = (const float*)d_in[15];
    const float* w_ih_l1_b = (const float*)d_in[16];
    const float* w_hh_l1_b = (const float*)d_in[17];
    const float* b_ih_l1_b = (const float*)d_in[18];
    const float* b_hh_l1_b = (const float*)d_in[19];
    const float* lin_w = (const float*)d_in[20];
    const float* lin_b = (const float*)d_in[21];
    const float* trans = (const float*)d_in[22];
    float* out = (float*)d_out;

    init_kernel<<<1, 512>>>();
    embed_kernel<<<(TT * EE) / 256, 256>>>(tokens, embed);

    gemm_kernel<<<dim3(16, 16, 2), 256>>>(w_ih_l0_f, b_ih_l0_f, b_hh_l0_f,
                                          w_ih_l0_b, b_ih_l0_b, b_hh_l0_b, 0, EE);
    lstm_layer<<<2 * GBD, 512>>>(w_hh_l0_f, w_hh_l0_b, 0, 0);

    gemm_kernel<<<dim3(16, 16, 2), 256>>>(w_ih_l1_f, b_ih_l1_f, b_hh_l1_f,
                                          w_ih_l1_b, b_ih_l1_b, b_hh_l1_b, 1, 2 * HH);
    lstm_layer<<<2 * GBD, 512>>>(w_hh_l1_f, w_hh_l1_b, 1, 2);

    linear_kernel<<<TT, 128>>>(lin_w, lin_b);
    crf_kernel<<<1, 768>>>(trans, tags, seq_len, out);
}

// round 12
// speedup vs baseline: 5.0990x; 1.2604x over previous
#include <cuda_runtime.h>
#include <cstdint>

#define TT 2048
#define EE 256
#define HH 512
#define GB 32          // blocks per direction in recurrent kernel
#define CPB 16         // cells per block
#define KK 48
#define NEGV -100000.0f
#define STARTT 45
#define ENDT 46

// ---------------- scratch (device globals; no allocation allowed) ----------------
__device__ float g_x[TT * EE];              // embedded tokens        2 MB
__device__ float g_proj0[TT * 4 * HH];      // input proj (fwd)      16 MB
__device__ float g_proj1[TT * 4 * HH];      // input proj (bwd)      16 MB
__device__ float g_h0[TT * 2 * HH];         // layer0 output          8 MB
__device__ float g_h1[TT * 2 * HH];         // layer1 output          8 MB
__device__ float g_feats[TT * KK];          // linear output
// packed {tag<<32 | h} per cell, double-buffered, per (layer,dir)
__device__ unsigned long long g_hx[4][2][HH];

#define FMA_F32X2(acc, a, b) \
    asm("fma.rn.f32x2 %0, %1, %2, %3;" : "=l"(acc) : "l"(a), "l"(b), "l"(acc))
#define UNPACK_F32X2(lo, hi, in) \
    asm("mov.b64 {%0, %1}, %2;" : "=f"(lo), "=f"(hi) : "l"(in))

__device__ __forceinline__ float tanh_approx(float x) {
    float r;
    asm("tanh.approx.f32 %0, %1;" : "=f"(r) : "f"(x));
    return r;
}

// ---------------- init: reset packed h slots every replay ----------------
__global__ void init_kernel() {
    int tid = threadIdx.x;
    unsigned long long* p = (unsigned long long*)g_hx;
    for (int i = tid; i < 4 * 2 * HH; i += 512) p[i] = 0ull;
}

// ---------------- embedding gather ----------------
__global__ void embed_kernel(const int* __restrict__ tok, const float* __restrict__ emb) {
    int i = blockIdx.x * 256 + threadIdx.x;        // i < TT*EE
    int t = i >> 8;
    int e = i & 255;
    g_x[i] = __ldg(&emb[tok[t] * EE + e]);
}

// ---------------- tiled SGEMM (dual: z=0 fwd weights -> g_proj0, z=1 bwd -> g_proj1)
__global__ __launch_bounds__(256) void gemm_kernel(const float* __restrict__ Wf,
                                                   const float* __restrict__ b1f,
                                                   const float* __restrict__ b2f,
                                                   const float* __restrict__ Wb,
                                                   const float* __restrict__ b1b,
                                                   const float* __restrict__ b2b,
                                                   int a_sel, int Kd) {
    const float* A = a_sel ? g_h0 : g_x;
    int zb = blockIdx.z;
    const float* W = zb ? Wb : Wf;
    const float* b1 = zb ? b1b : b1f;
    const float* b2 = zb ? b2b : b2f;
    float* C = zb ? g_proj1 : g_proj0;
    const int N = 2048;

    __shared__ float As[16][128];
    __shared__ float Ws[16][128];

    int tid = threadIdx.x;
    int m0 = blockIdx.y * 128, n0 = blockIdx.x * 128;
    int tx = tid & 15, ty = tid >> 4;
    int lr = tid >> 1;
    int kq = (tid & 1) * 8;

    float acc[8][8];
#pragma unroll
    for (int i = 0; i < 8; i++)
#pragma unroll
        for (int j = 0; j < 8; j++) acc[i][j] = 0.f;

    for (int kt = 0; kt < Kd; kt += 16) {
        float4 a0 = *(const float4*)&A[(m0 + lr) * Kd + kt + kq];
        float4 a1 = *(const float4*)&A[(m0 + lr) * Kd + kt + kq + 4];
        float4 w0 = *(const float4*)&W[(n0 + lr) * Kd + kt + kq];
        float4 w1 = *(const float4*)&W[(n0 + lr) * Kd + kt + kq + 4];
        __syncthreads();
        As[kq + 0][lr] = a0.x; As[kq + 1][lr] = a0.y; As[kq + 2][lr] = a0.z; As[kq + 3][lr] = a0.w;
        As[kq + 4][lr] = a1.x; As[kq + 5][lr] = a1.y; As[kq + 6][lr] = a1.z; As[kq + 7][lr] = a1.w;
        Ws[kq + 0][lr] = w0.x; Ws[kq + 1][lr] = w0.y; Ws[kq + 2][lr] = w0.z; Ws[kq + 3][lr] = w0.w;
        Ws[kq + 4][lr] = w1.x; Ws[kq + 5][lr] = w1.y; Ws[kq + 6][lr] = w1.z; Ws[kq + 7][lr] = w1.w;
        __syncthreads();
#pragma unroll
        for (int k = 0; k < 16; k++) {
            float4 av0 = *(const float4*)&As[k][ty * 8];
            float4 av1 = *(const float4*)&As[k][ty * 8 + 4];
            float4 bv0 = *(const float4*)&Ws[k][tx * 8];
            float4 bv1 = *(const float4*)&Ws[k][tx * 8 + 4];
            float a_[8] = {av0.x, av0.y, av0.z, av0.w, av1.x, av1.y, av1.z, av1.w};
            float b_[8] = {bv0.x, bv0.y, bv0.z, bv0.w, bv1.x, bv1.y, bv1.z, bv1.w};
#pragma unroll
            for (int i = 0; i < 8; i++)
#pragma unroll
                for (int j = 0; j < 8; j++) acc[i][j] += a_[i] * b_[j];
        }
    }

#pragma unroll
    for (int i = 0; i < 8; i++) {
        int row = m0 + ty * 8 + i;
#pragma unroll
        for (int j0 = 0; j0 < 8; j0 += 4) {
            int col = n0 + tx * 8 + j0;
            float4 v;
            v.x = acc[i][j0 + 0] + __ldg(&b1[col + 0]) + __ldg(&b2[col + 0]);
            v.y = acc[i][j0 + 1] + __ldg(&b1[col + 1]) + __ldg(&b2[col + 1]);
            v.z = acc[i][j0 + 2] + __ldg(&b1[col + 2]) + __ldg(&b2[col + 2]);
            v.w = acc[i][j0 + 3] + __ldg(&b1[col + 3]) + __ldg(&b2[col + 3]);
            *(float4*)&C[row * N + col] = v;
        }
    }
}

// ---------------- persistent bidirectional LSTM layer ----------------
// grid = 64 blocks: [0,32) forward, [32,64) backward. 512 threads = 16 warps.
// Warp w computes all 4 gates of cell b*16+w; W_hh rows live in registers
// (R6 layout: each loaded h float4 is reused by all 4 gates -> 4 LDS/thread).
// Sync: packed {tag,h} u64 slots, one st.cg.u64 publish, per-slot polls with
// 8-add backoff. Activations via tanh.approx (MUFU.TANH).
__global__ __launch_bounds__(512) void lstm_layer(const float* __restrict__ whhf,
                                                  const float* __restrict__ whhb,
                                                  int outsel, int cb) {
    __shared__ float hsm[2][HH];    // double-buffered staged h

    int dir = (blockIdx.x >= GB) ? 1 : 0;
    int b = blockIdx.x - dir * GB;
    const float* proj = dir ? g_proj1 : g_proj0;
    const float* whh = dir ? whhb : whhf;
    float* hout = outsel ? g_h1 : g_h0;
    int tid = threadIdx.x;
    int w = tid >> 5, lane = tid & 31;
    int cell = b * CPB + w;

    // W_hh rows for this cell's 4 gates, packed as f32x2 pairs in registers.
    ulonglong2 wp[4][4];
#pragma unroll
    for (int g = 0; g < 4; g++) {
        const ulonglong2* row = (const ulonglong2*)(whh + (g * HH + cell) * HH);
#pragma unroll
        for (int j = 0; j < 4; j++) wp[g][j] = row[j * 32 + lane];
    }

    unsigned long long* hx0 = g_hx[cb + dir][0];
    unsigned long long* hx1 = g_hx[cb + dir][1];

    float c = 0.f;
    float pv = 0.f;
    {
        int tt0 = dir ? (TT - 1) : 0;
        if (lane < 4) pv = __ldg(&proj[tt0 * 2048 + lane * HH + cell]);
    }

    unsigned junk = tid;
    for (int t = 0; t < TT; t++) {
        int tt = dir ? (TT - 1 - t) : t;
        unsigned long long* rbuf = (t & 1) ? hx1 : hx0;
        unsigned long long* wbuf = (t & 1) ? hx0 : hx1;
        float* hs = hsm[t & 1];

        // stage: poll own slot; tag>=t means value from step t-1 present.
        {
            unsigned long long v;
            const unsigned long long* sp = &rbuf[tid];
            asm volatile("ld.global.cg.u64 %0, [%1];" : "=l"(v) : "l"(sp) : "memory");
            while ((int)(v >> 32) < t) {
#pragma unroll
                for (int i = 0; i < 8; i++)
                    asm volatile("add.u32 %0, %0, 1;" : "+r"(junk));
                asm volatile("ld.global.cg.u64 %0, [%1];" : "=l"(v) : "l"(sp) : "memory");
            }
            hs[tid] = __uint_as_float((unsigned)v);
        }

        float pvc = pv;
        if (t + 1 < TT && lane < 4) {
            int ttn = dir ? (TT - 2 - t) : (t + 1);
            pv = __ldg(&proj[ttn * 2048 + lane * HH + cell]);
        }
        __syncthreads();

        // 4 dot-512s via packed f32x2 FMA (each h load reused by all 4 gates)
        unsigned long long acc0 = 0, acc1 = 0, acc2 = 0, acc3 = 0;
        const ulonglong2* hp = (const ulonglong2*)hs;
#pragma unroll
        for (int j = 0; j < 4; j++) {
            ulonglong2 hv = hp[j * 32 + lane];
            FMA_F32X2(acc0, wp[0][j].x, hv.x);
            FMA_F32X2(acc0, wp[0][j].y, hv.y);
            FMA_F32X2(acc1, wp[1][j].x, hv.x);
            FMA_F32X2(acc1, wp[1][j].y, hv.y);
            FMA_F32X2(acc2, wp[2][j].x, hv.x);
            FMA_F32X2(acc2, wp[2][j].y, hv.y);
            FMA_F32X2(acc3, wp[3][j].x, hv.x);
            FMA_F32X2(acc3, wp[3][j].y, hv.y);
        }
        float g0, g1, g2, g3;
        {
            float lo, hi;
            UNPACK_F32X2(lo, hi, acc0); g0 = lo + hi;
            UNPACK_F32X2(lo, hi, acc1); g1 = lo + hi;
            UNPACK_F32X2(lo, hi, acc2); g2 = lo + hi;
            UNPACK_F32X2(lo, hi, acc3); g3 = lo + hi;
        }
        if (lane == 0) g0 += pvc;
        else if (lane == 1) g1 += pvc;
        else if (lane == 2) g2 += pvc;
        else if (lane == 3) g3 += pvc;

#pragma unroll
        for (int o = 16; o >= 1; o >>= 1) {
            g0 += __shfl_xor_sync(0xffffffffu, g0, o);
            g1 += __shfl_xor_sync(0xffffffffu, g1, o);
            g2 += __shfl_xor_sync(0xffffffffu, g2, o);
            g3 += __shfl_xor_sync(0xffffffffu, g3, o);
        }

        // lane-distributed activations via tanh.approx:
        // sigmoid(x) = 0.5*tanh(0.5x)+0.5 ; gate 2 (g) is plain tanh.
        float arg = 0.5f * g0;
        arg = (lane == 1) ? 0.5f * g1 : arg;
        arg = (lane == 2) ? g2 : arg;
        arg = (lane == 3) ? 0.5f * g3 : arg;
        float tv = tanh_approx(arg);
        float y = (lane == 2) ? tv : fmaf(0.5f, tv, 0.5f);
        float iv = __shfl_sync(0xffffffffu, y, 0);
        float fv = __shfl_sync(0xffffffffu, y, 1);
        float gv = __shfl_sync(0xffffffffu, y, 2);
        float ov = __shfl_sync(0xffffffffu, y, 3);
        c = fv * c + iv * gv;          // uniform across lanes
        float h = ov * tanh_approx(c);

        if (lane == 0) {
            unsigned long long pkt =
                ((unsigned long long)(unsigned)(t + 1) << 32) | (unsigned long long)__float_as_uint(h);
            asm volatile("st.global.cg.u64 [%0], %1;" :: "l"(&wbuf[cell]), "l"(pkt) : "memory");
            hout[tt * (2 * HH) + dir * HH + cell] = h;
        }
        // hsm parity reuse is gated by the next step's barrier
    }
}

// ---------------- linear:  feats[T,K] = h1 @ lin_w^T + lin_b ----------------
__global__ __launch_bounds__(128) void linear_kernel(const float* __restrict__ lw,
                                                     const float* __restrict__ lb) {
    __shared__ float hs[2 * HH];
    int t = blockIdx.x, tid = threadIdx.x;
    for (int i = tid; i < (2 * HH) / 4; i += 128)
        ((float4*)hs)[i] = ((const float4*)(g_h1 + t * 2 * HH))[i];
    __syncthreads();
    int warp = tid >> 5, lane = tid & 31;
    for (int jj = warp; jj < KK; jj += 4) {
        const float* wrow = lw + jj * (2 * HH);
        float acc = 0.f;
#pragma unroll 8
        for (int k = 0; k < 32; k++) {
            int d = lane + 32 * k;
            acc += hs[d] * __ldg(&wrow[d]);
        }
        acc += __shfl_xor_sync(0xffffffffu, acc, 16);
        acc += __shfl_xor_sync(0xffffffffu, acc, 8);
        acc += __shfl_xor_sync(0xffffffffu, acc, 4);
        acc += __shfl_xor_sync(0xffffffffu, acc, 2);
        acc += __shfl_xor_sync(0xffffffffu, acc, 1);
        if (lane == 0) g_feats[t * KK + jj] = acc + __ldg(&lb[jj]);
    }
}

// ---------------- CRF forward scan + gold score + final output ----------------
__global__ __launch_bounds__(768) void crf_kernel(const float* __restrict__ trans,
                                                  const int* __restrict__ tags,
                                                  const int* __restrict__ seq_len,
                                                  float* __restrict__ out) {
    __shared__ float tr[KK * KK];
    __shared__ float alpha[2][KK];
    __shared__ float red[768];
    __shared__ float s_score;
    int tid = threadIdx.x;

    for (int i = tid; i < KK * KK; i += 768) tr[i] = trans[i];

    float sc = 0.f;
    for (int k = tid; k < TT; k += 768) {
        int cur = tags[k];
        int prev = (k == 0) ? STARTT : tags[k - 1];
        sc += __ldg(&trans[cur * KK + prev]) + __ldg(&g_feats[k * KK + cur]);
    }
    red[tid] = sc;
    if (tid < KK) alpha[0][tid] = (tid == STARTT) ? 0.f : NEGV;
    __syncthreads();
    if (tid == 0) {
        float s = 0.f;
        for (int i = 0; i < 768; i++) s += red[i];
        s += tr[ENDT * KK + tags[TT - 1]];
        s_score = s;
    }
    __syncthreads();

    int j = tid >> 4, l = tid & 15;
    for (int t = 0; t < TT; t++) {
        const float* a = alpha[t & 1];
        float* an = alpha[(t + 1) & 1];
        float v0 = a[l]      + tr[j * KK + l];
        float v1 = a[l + 16] + tr[j * KK + l + 16];
        float v2 = a[l + 32] + tr[j * KK + l + 32];
        float m = fmaxf(v0, fmaxf(v1, v2));
#pragma unroll
        for (int o = 8; o >= 1; o >>= 1) m = fmaxf(m, __shfl_xor_sync(0xffffffffu, m, o));
        float s = __expf(v0 - m) + __expf(v1 - m) + __expf(v2 - m);
#pragma unroll
        for (int o = 8; o >= 1; o >>= 1) s += __shfl_xor_sync(0xffffffffu, s, o);
        if (l == 0) an[j] = m + __logf(s) + __ldg(&g_feats[t * KK + j]);
        __syncthreads();
    }

    if (tid == 0) {
        const float* a = alpha[TT & 1];
        float m = -3.4e38f;
        for (int i = 0; i < KK; i++) m = fmaxf(m, a[i] + tr[ENDT * KK + i]);
        float s = 0.f;
        for (int i = 0; i < KK; i++) s += __expf(a[i] + tr[ENDT * KK + i] - m);
        float logz = m + __logf(s);
        out[0] = (logz - s_score) / (float)seq_len[0];
    }
}

// ---------------- launch ----------------
extern "C" void kernel_launch(void* const* d_in, const int* in_sizes, int n_in,
                              void* d_out, int out_size) {
    const int* tokens = (const int*)d_in[0];
    const int* tags = (const int*)d_in[1];
    const int* seq_len = (const int*)d_in[2];
    const float* embed = (const float*)d_in[3];
    const float* w_ih_l0_f = (const float*)d_in[4];
    const float* w_hh_l0_f = (const float*)d_in[5];
    const float* b_ih_l0_f = (const float*)d_in[6];
    const float* b_hh_l0_f = (const float*)d_in[7];
    const float* w_ih_l0_b = (const float*)d_in[8];
    const float* w_hh_l0_b = (const float*)d_in[9];
    const float* b_ih_l0_b = (const float*)d_in[10];
    const float* b_hh_l0_b = (const float*)d_in[11];
    const float* w_ih_l1_f = (const float*)d_in[12];
    const float* w_hh_l1_f = (const float*)d_in[13];
    const float* b_ih_l1_f = (const float*)d_in[14];
    const float* b_hh_l1_f = (const float*)d_in[15];
    const float* w_ih_l1_b = (const float*)d_in[16];
    const float* w_hh_l1_b = (const float*)d_in[17];
    const float* b_ih_l1_b = (const float*)d_in[18];
    const float* b_hh_l1_b = (const float*)d_in[19];
    const float* lin_w = (const float*)d_in[20];
    const float* lin_b = (const float*)d_in[21];
    const float* trans = (const float*)d_in[22];
    float* out = (float*)d_out;

    init_kernel<<<1, 512>>>();
    embed_kernel<<<(TT * EE) / 256, 256>>>(tokens, embed);

    gemm_kernel<<<dim3(16, 16, 2), 256>>>(w_ih_l0_f, b_ih_l0_f, b_hh_l0_f,
                                          w_ih_l0_b, b_ih_l0_b, b_hh_l0_b, 0, EE);
    lstm_layer<<<2 * GB, 512>>>(w_hh_l0_f, w_hh_l0_b, 0, 0);

    gemm_kernel<<<dim3(16, 16, 2), 256>>>(w_ih_l1_f, b_ih_l1_f, b_hh_l1_f,
                                          w_ih_l1_b, b_ih_l1_b, b_hh_l1_b, 1, 2 * HH);
    lstm_layer<<<2 * GB, 512>>>(w_hh_l1_f, w_hh_l1_b, 1, 2);

    linear_kernel<<<TT, 128>>>(lin_w, lin_b);
    crf_kernel<<<1, 768>>>(trans, tags, seq_len, out);
}